// round 8
// baseline (speedup 1.0000x reference)
#include <cuda_runtime.h>
#include <cuda_fp16.h>
#include <mma.h>
#include <cstdint>
#include <cstddef>
using namespace nvcuda;

#define Bb 32
#define Tt 64
#define Ee 512
#define Hh 512
#define Vv 32000
#define G4 2048
#define Mm 2048   // T*B rows; Gx rows r = t*32+b; hs rows rr = b*64+t

// ---------------- static device scratch (no allocations allowed) -----------
__device__ __half g_XH[Mm * Ee];
__device__ __half g_XL[Mm * Ee];
__device__ __half g_WihH[G4 * Ee];
__device__ __half g_WihL[G4 * Ee];
__device__ __half g_WoutH[(size_t)Vv * Hh];
__device__ __half g_WoutL[(size_t)Vv * Hh];
__device__ __half g_hsH[Mm * Hh];
__device__ __half g_hsL[Mm * Hh];
__device__ float  g_GxT[(size_t)G4 * Mm];   // [gatecol][row r=t*32+b]
__device__ float  g_h[2][Bb * Hh];          // ping-pong recurrent h
__device__ float  g_bT0[16 * G4];           // replicated bias tile b_ih+b_hh
__device__ float  g_bT1[16 * Vv];           // replicated bias tile b_out
__device__ int    g_capIdx[Bb * Tt];        // decoded caption token indices
__device__ unsigned g_bcount;               // grid barrier counter

// ---------------- helpers ---------------------------------------------------
__device__ __forceinline__ unsigned long long pk2(float x, float y) {
    unsigned long long r; asm("mov.b64 %0, {%1, %2};" : "=l"(r) : "f"(x), "f"(y));
    return r;
}
__device__ __forceinline__ void upk2(unsigned long long a, float& x, float& y) {
    asm("mov.b64 {%0, %1}, %2;" : "=f"(x), "=f"(y) : "l"(a));
}
__device__ __forceinline__ unsigned long long ffma2(unsigned long long a,
                                                    unsigned long long b,
                                                    unsigned long long c) {
    unsigned long long d;
    asm("fma.rn.f32x2 %0, %1, %2, %3;" : "=l"(d) : "l"(a), "l"(b), "l"(c));
    return d;
}
__device__ __forceinline__ unsigned smaddr(const void* p) {
    return (unsigned)__cvta_generic_to_shared(p);
}
__device__ __forceinline__ void cpa16(void* s, const void* g) {
    asm volatile("cp.async.cg.shared.global [%0], [%1], 16;\n"
                 :: "r"(smaddr(s)), "l"(g));
}
__device__ __forceinline__ void split16(float v, __half& hi, __half& lo) {
    hi = __float2half_rn(v);
    lo = __float2half_rn(v - __half2float(hi));
}

// ---------------- caption dtype sniff + decode ------------------------------
// The reference says int64, but JAX without x64 silently emits int32. Detect:
// view buffer as int32; probe the first 2048 slots (in-bounds either way).
// int64 layout => odd slots are all high-words of nonnegative tokens => all 0.
// int32 layout => odd slots are real tokens (1024 random tokens all-zero: ~0).
__global__ void build_cap(const int* __restrict__ cap32) {
    __shared__ int anyOdd;
    if (threadIdx.x == 0) anyOdd = 0;
    __syncthreads();
    int local = 0;
    for (int i = threadIdx.x; i < (Bb * Tt) / 2; i += blockDim.x)
        local |= cap32[2 * i + 1];
    if (local) atomicOr(&anyOdd, 1);
    __syncthreads();
    bool is64 = (anyOdd == 0);
    for (int i = threadIdx.x; i < Bb * Tt; i += blockDim.x) {
        int idx = is64 ? cap32[2 * i] : cap32[i];
        idx = idx < 0 ? 0 : (idx >= Vv ? Vv - 1 : idx);   // clamp: no OOB ever
        g_capIdx[i] = idx;
    }
}

// ---------------- prep kernels ----------------------------------------------
__global__ void conv_split(const float* __restrict__ src, int which, size_t n) {
    __half* dh = which ? g_WoutH : g_WihH;
    __half* dl = which ? g_WoutL : g_WihL;
    size_t st = (size_t)gridDim.x * blockDim.x;
    for (size_t i = (size_t)blockIdx.x * blockDim.x + threadIdx.x; i < n; i += st) {
        __half h, l; split16(src[i], h, l);
        dh[i] = h; dl[i] = l;
    }
}

__global__ void build_x(const float* __restrict__ feat,
                        const float* __restrict__ emb) {
    size_t st = (size_t)gridDim.x * blockDim.x;
    for (size_t i = (size_t)blockIdx.x * blockDim.x + threadIdx.x;
         i < (size_t)Mm * Ee; i += st) {
        int r = (int)(i >> 9);
        int e = (int)(i & 511);
        int t = r >> 5, b = r & 31;
        float v;
        if (t == 0) {
            v = feat[b * Ee + e];
        } else {
            int idx = g_capIdx[b * Tt + t];
            v = emb[(size_t)idx * Ee + e];
        }
        __half h, l; split16(v, h, l);
        g_XH[i] = h; g_XL[i] = l;
    }
}

__global__ void build_bias(const float* __restrict__ b_ih,
                           const float* __restrict__ b_hh,
                           const float* __restrict__ b_out) {
    size_t st = (size_t)gridDim.x * blockDim.x;
    for (size_t i = (size_t)blockIdx.x * blockDim.x + threadIdx.x;
         i < (size_t)16 * Vv; i += st)
        g_bT1[i] = b_out[i % Vv];
    for (size_t i = (size_t)blockIdx.x * blockDim.x + threadIdx.x;
         i < (size_t)16 * G4; i += st) {
        int j = (int)(i & 2047);
        g_bT0[i] = b_ih[j] + b_hh[j];
    }
}

__global__ void reset_k() {
    if (threadIdx.x == 0) g_bcount = 0u;
    for (int i = threadIdx.x; i < Bb * Hh; i += blockDim.x) g_h[0][i] = 0.f;
}

// ---------------- split-fp16 wmma GEMM --------------------------------------
// C[M x N] = A[M x 512] * Bw[N x 512]^T + bias, fp32-class via 3-mma split.
// mode 0: A=X (rows t*32+b), Bw=W_ih -> g_GxT transposed store, bias tile bT0.
// mode 1: A=hs (rows b*64+t), Bw=W_out -> Cout logits [b][t][v], bias tile bT1.
__global__ __launch_bounds__(256)
void gemm_split(float* __restrict__ Cout, int mode) {
    __shared__ __half sA[2][2][128 * 16];   // [stage][hi/lo]
    __shared__ __half sB[2][2][128 * 16];

    const __half *AH, *AL, *BH, *BL; const float* bT; int Nfull;
    if (mode == 0) { AH = g_XH;  AL = g_XL;  BH = g_WihH;  BL = g_WihL;
                     bT = g_bT0; Nfull = G4; }
    else           { AH = g_hsH; AL = g_hsL; BH = g_WoutH; BL = g_WoutL;
                     bT = g_bT1; Nfull = Vv; }

    int tid = threadIdx.x, wid = tid >> 5;
    int m0 = blockIdx.y * 128, n0 = blockIdx.x * 128;
    int wm = (wid >> 2) * 64, wn = (wid & 3) * 32;

    // accumulators initialized from the replicated global bias tile
    wmma::fragment<wmma::accumulator, 16, 16, 16, float> acc[4][2];
    #pragma unroll
    for (int mi = 0; mi < 4; mi++)
        #pragma unroll
        for (int ni = 0; ni < 2; ni++)
            wmma::load_matrix_sync(acc[mi][ni], bT + (n0 + wn + ni * 16),
                                   Nfull, wmma::mem_row_major);

    auto loadStage = [&](int ks, int st) {
        int kb = ks * 16;
        #pragma unroll
        for (int i = 0; i < 4; i++) {
            int c = i * 256 + tid;            // 1024 16B chunks total
            int cc = c & 255;
            int row = cc >> 1, q = cc & 1;
            const __half* gp; __half* sp;
            if (i == 0)      { gp = AH + (size_t)(m0 + row) * 512 + kb + q * 8;
                               sp = &sA[st][0][row * 16 + q * 8]; }
            else if (i == 1) { gp = AL + (size_t)(m0 + row) * 512 + kb + q * 8;
                               sp = &sA[st][1][row * 16 + q * 8]; }
            else if (i == 2) { gp = BH + (size_t)(n0 + row) * 512 + kb + q * 8;
                               sp = &sB[st][0][row * 16 + q * 8]; }
            else             { gp = BL + (size_t)(n0 + row) * 512 + kb + q * 8;
                               sp = &sB[st][1][row * 16 + q * 8]; }
            cpa16(sp, gp);
        }
    };

    loadStage(0, 0);
    asm volatile("cp.async.commit_group;\n");

    #pragma unroll 1
    for (int ks = 0; ks < 32; ks++) {
        if (ks < 31) {
            loadStage(ks + 1, (ks + 1) & 1);
            asm volatile("cp.async.commit_group;\n");
            asm volatile("cp.async.wait_group 1;\n");
        } else {
            asm volatile("cp.async.wait_group 0;\n");
        }
        __syncthreads();
        int st = ks & 1;

        wmma::fragment<wmma::matrix_b, 16, 16, 16, __half, wmma::col_major> fb[2], fbl[2];
        #pragma unroll
        for (int ni = 0; ni < 2; ni++) {
            wmma::load_matrix_sync(fb[ni],  &sB[st][0][(wn + ni * 16) * 16], 16);
            wmma::load_matrix_sync(fbl[ni], &sB[st][1][(wn + ni * 16) * 16], 16);
        }
        #pragma unroll
        for (int mi = 0; mi < 4; mi++) {
            wmma::fragment<wmma::matrix_a, 16, 16, 16, __half, wmma::row_major> fa, fal;
            wmma::load_matrix_sync(fa,  &sA[st][0][(wm + mi * 16) * 16], 16);
            wmma::load_matrix_sync(fal, &sA[st][1][(wm + mi * 16) * 16], 16);
            #pragma unroll
            for (int ni = 0; ni < 2; ni++) {
                wmma::mma_sync(acc[mi][ni], fa,  fb[ni],  acc[mi][ni]);
                wmma::mma_sync(acc[mi][ni], fa,  fbl[ni], acc[mi][ni]);
                wmma::mma_sync(acc[mi][ni], fal, fb[ni],  acc[mi][ni]);
            }
        }
        __syncthreads();
    }

    if (mode == 0) {
        #pragma unroll
        for (int mi = 0; mi < 4; mi++)
            #pragma unroll
            for (int ni = 0; ni < 2; ni++)
                wmma::store_matrix_sync(
                    g_GxT + (size_t)(n0 + wn + ni * 16) * Mm + (m0 + wm + mi * 16),
                    acc[mi][ni], Mm, wmma::mem_col_major);
    } else {
        #pragma unroll
        for (int mi = 0; mi < 4; mi++)
            #pragma unroll
            for (int ni = 0; ni < 2; ni++)
                wmma::store_matrix_sync(
                    Cout + (size_t)(m0 + wm + mi * 16) * Vv + (n0 + wn + ni * 16),
                    acc[mi][ni], Vv, wmma::mem_row_major);
    }
}

// ---------------- persistent LSTM recurrence (exact fp32) -------------------
// 128 CTAs x 256 threads, all resident (1 CTA/SM, single wave).
// CTA n: hf=n&1 (batch half), ug=n>>1. Warp w: unit u=ug*8+w, gate cols
// {u, 512+u, 1024+u, 1536+u}. Lane owns k-slice [lane*16, lane*16+16) of W_hh
// in registers. Lane batch b = hf*16 + (lane&15) (lanes l, l+16 duplicate).
// h staged in smem layout sh2[(j*16+bl)*32 + lane] (float2, k=lane*16+2j).
#define REC_CTAS 128

__global__ __launch_bounds__(256)
void lstm_kernel(const float* __restrict__ Whh) {
    __shared__ float2 sh2[8 * 16 * 32];   // 32 KB

    int tid = threadIdx.x, lane = tid & 31, w = tid >> 5;
    int n = blockIdx.x;
    int hf = n & 1;
    int ug = n >> 1;
    int u  = ug * 8 + w;
    int b  = hf * 16 + (lane & 15);

    unsigned long long w2[4][8];
    #pragma unroll
    for (int cc = 0; cc < 4; cc++) {
        const float2* wr = (const float2*)&Whh[(size_t)(cc * 512 + u) * 512];
        #pragma unroll
        for (int j = 0; j < 8; j++) {
            float2 v = wr[lane * 8 + j];
            w2[cc][j] = pk2(v.x, v.y);
        }
    }

    float cst = 0.f;

    for (int t = 0; t < 64; t++) {
        const float4* hc = (const float4*)g_h[t & 1];
        #pragma unroll
        for (int i = 0; i < 8; i++) {
            int q = i * 256 + tid;
            int bl = q >> 7;
            int k4 = q & 127;
            float4 v = __ldcg(hc + (size_t)(hf * 16 + bl) * 128 + k4);
            int k2a = 2 * k4, k2b = 2 * k4 + 1;
            sh2[((k2a & 7) * 16 + bl) * 32 + (k2a >> 3)] = make_float2(v.x, v.y);
            sh2[((k2b & 7) * 16 + bl) * 32 + (k2b >> 3)] = make_float2(v.z, v.w);
        }
        __syncthreads();

        unsigned long long a2[4][16];
        #pragma unroll
        for (int cc = 0; cc < 4; cc++)
            #pragma unroll
            for (int i = 0; i < 16; i++) a2[cc][i] = 0ull;

        #pragma unroll
        for (int j = 0; j < 8; j++) {
            #pragma unroll
            for (int bl = 0; bl < 16; bl++) {
                float2 hv = sh2[(j * 16 + bl) * 32 + lane];
                unsigned long long h2v = pk2(hv.x, hv.y);
                #pragma unroll
                for (int cc = 0; cc < 4; cc++)
                    a2[cc][bl] = ffma2(w2[cc][j], h2v, a2[cc][bl]);
            }
        }

        float gate[4];
        #pragma unroll
        for (int cc = 0; cc < 4; cc++) {
            float s[16];
            #pragma unroll
            for (int i = 0; i < 16; i++) {
                float x, y; upk2(a2[cc][i], x, y); s[i] = x + y;
            }
            int nb = 16;
            #pragma unroll
            for (int off = 8; off >= 1; off >>= 1) {
                int hn = nb >> 1;
                bool hi = (lane & off) != 0;
                #pragma unroll
                for (int i = 0; i < hn; i++) {
                    float give = hi ? s[i] : s[i + hn];
                    float keep = hi ? s[i + hn] : s[i];
                    float got  = __shfl_xor_sync(0xffffffffu, give, off);
                    s[i] = keep + got;
                }
                nb = hn;
            }
            s[0] += __shfl_xor_sync(0xffffffffu, s[0], 16);
            gate[cc] = s[0];
        }

        int row = t * 32 + b;
        #pragma unroll
        for (int cc = 0; cc < 4; cc++)
            gate[cc] += __ldg(&g_GxT[(size_t)(cc * 512 + u) * Mm + row]);

        float ig = 1.f / (1.f + expf(-gate[0]));
        float fg = 1.f / (1.f + expf(-gate[1]));
        float gg = tanhf(gate[2]);
        float og = 1.f / (1.f + expf(-gate[3]));
        cst = fg * cst + ig * gg;
        float hN = og * tanhf(cst);

        if (lane < 16) {
            g_h[(t + 1) & 1][b * 512 + u] = hN;
            int rr = b * 64 + t;                       // hs rows = output rows
            __half hh, hl; split16(hN, hh, hl);
            g_hsH[(size_t)rr * 512 + u] = hh;
            g_hsL[(size_t)rr * 512 + u] = hl;
        }

        __threadfence();
        __syncthreads();
        if (tid == 0) {
            atomicAdd(&g_bcount, 1u);
            unsigned tgt = (unsigned)REC_CTAS * (unsigned)(t + 1);
            while (*(volatile unsigned*)&g_bcount < tgt) { __nanosleep(32); }
            __threadfence();
        }
        __syncthreads();
    }
}

// ---------------- launch -----------------------------------------------------
extern "C" void kernel_launch(void* const* d_in, const int* in_sizes, int n_in,
                              void* d_out, int out_size) {
    const float* feat  = (const float*)d_in[0];
    const int*   cap32 = (const int*)d_in[1];     // dtype sniffed on device
    const float* W_ih  = (const float*)d_in[2];
    const float* W_hh  = (const float*)d_in[3];
    const float* b_ih  = (const float*)d_in[4];
    const float* b_hh  = (const float*)d_in[5];
    const float* W_out = (const float*)d_in[6];
    const float* b_out = (const float*)d_in[7];
    const float* emb   = (const float*)d_in[8];
    float* out = (float*)d_out;

    build_cap<<<1, 256>>>(cap32);
    conv_split<<<512, 256>>>(W_ih, 0, (size_t)G4 * Ee);
    conv_split<<<2048, 256>>>(W_out, 1, (size_t)Vv * Hh);
    build_x<<<512, 256>>>(feat, emb);
    build_bias<<<512, 256>>>(b_ih, b_hh, b_out);
    reset_k<<<1, 256>>>();

    gemm_split<<<dim3(G4 / 128, Mm / 128), 256>>>(nullptr, 0);
    lstm_kernel<<<REC_CTAS, 256>>>(W_hh);
    gemm_split<<<dim3(Vv / 128, Mm / 128), 256>>>(out, 1);
}

// round 12
// speedup vs baseline: 1.0278x; 1.0278x over previous
#include <cuda_runtime.h>
#include <cuda_fp16.h>
#include <mma.h>
#include <cstdint>
#include <cstddef>
using namespace nvcuda;

#define Bb 32
#define Tt 64
#define Ee 512
#define Hh 512
#define Vv 32000
#define G4 2048
#define Mm 2048   // T*B rows; Gx rows r = t*32+b; V-GEMM A rows rr = b*64+t

// ---------------- static device scratch (no allocations allowed) -----------
__device__ __half g_XH[Mm * Ee];
__device__ __half g_XL[Mm * Ee];
__device__ __half g_WihH[G4 * Ee];
__device__ __half g_WihL[G4 * Ee];
__device__ __half g_WoutH[(size_t)Vv * Hh];
__device__ __half g_WoutL[(size_t)Vv * Hh];
__device__ __half g_hsH[Mm * Hh];           // split h history, rows rr=b*64+t
__device__ __half g_hsL[Mm * Hh];
__device__ float  g_GxT[(size_t)G4 * Mm];   // [gatecol][row r=t*32+b]
__device__ float  g_h[2][Bb * Hh];          // ping-pong recurrent h
__device__ float  g_bT0[16 * G4];           // replicated bias tile b_ih+b_hh
__device__ int    g_capIdx[Bb * Tt];        // decoded caption token indices
__device__ unsigned g_bcount;               // grid barrier counter

// ---------------- helpers ---------------------------------------------------
__device__ __forceinline__ unsigned long long pk2(float x, float y) {
    unsigned long long r; asm("mov.b64 %0, {%1, %2};" : "=l"(r) : "f"(x), "f"(y));
    return r;
}
__device__ __forceinline__ void upk2(unsigned long long a, float& x, float& y) {
    asm("mov.b64 {%0, %1}, %2;" : "=f"(x), "=f"(y) : "l"(a));
}
__device__ __forceinline__ unsigned long long ffma2(unsigned long long a,
                                                    unsigned long long b,
                                                    unsigned long long c) {
    unsigned long long d;
    asm("fma.rn.f32x2 %0, %1, %2, %3;" : "=l"(d) : "l"(a), "l"(b), "l"(c));
    return d;
}
__device__ __forceinline__ unsigned smaddr(const void* p) {
    return (unsigned)__cvta_generic_to_shared(p);
}
__device__ __forceinline__ void cpa16(void* s, const void* g) {
    asm volatile("cp.async.cg.shared.global [%0], [%1], 16;\n"
                 :: "r"(smaddr(s)), "l"(g));
}
__device__ __forceinline__ void split16(float v, __half& hi, __half& lo) {
    hi = __float2half_rn(v);
    lo = __float2half_rn(v - __half2float(hi));
}

// ---------------- fused small prep ------------------------------------------
// block 0: caption dtype sniff + decode, h0/counter reset. all blocks: bias tile
__global__ void prep_misc(const int* __restrict__ cap32,
                          const float* __restrict__ b_ih,
                          const float* __restrict__ b_hh) {
    if (blockIdx.x == 0) {
        __shared__ int anyOdd;
        if (threadIdx.x == 0) { anyOdd = 0; g_bcount = 0u; }
        __syncthreads();
        int local = 0;
        for (int i = threadIdx.x; i < (Bb * Tt) / 2; i += blockDim.x)
            local |= cap32[2 * i + 1];
        if (local) atomicOr(&anyOdd, 1);
        __syncthreads();
        bool is64 = (anyOdd == 0);
        for (int i = threadIdx.x; i < Bb * Tt; i += blockDim.x) {
            int idx = is64 ? cap32[2 * i] : cap32[i];
            idx = idx < 0 ? 0 : (idx >= Vv ? Vv - 1 : idx);
            g_capIdx[i] = idx;
        }
        for (int i = threadIdx.x; i < Bb * Hh; i += blockDim.x) g_h[0][i] = 0.f;
    }
    size_t st = (size_t)gridDim.x * blockDim.x;
    for (size_t i = (size_t)blockIdx.x * blockDim.x + threadIdx.x;
         i < (size_t)16 * G4; i += st) {
        int j = (int)(i & 2047);
        g_bT0[i] = b_ih[j] + b_hh[j];
    }
}

// ---------------- fused weight conversion ------------------------------------
__global__ void conv_weights(const float* __restrict__ W_ih,
                             const float* __restrict__ W_out) {
    const size_t n1 = (size_t)G4 * Ee;
    const size_t n2 = (size_t)Vv * Hh;
    size_t st = (size_t)gridDim.x * blockDim.x;
    for (size_t i = (size_t)blockIdx.x * blockDim.x + threadIdx.x;
         i < n1 + n2; i += st) {
        if (i < n1) {
            __half h, l; split16(W_ih[i], h, l);
            g_WihH[i] = h; g_WihL[i] = l;
        } else {
            size_t j = i - n1;
            __half h, l; split16(W_out[j], h, l);
            g_WoutH[j] = h; g_WoutL[j] = l;
        }
    }
}

__global__ void build_x(const float* __restrict__ feat,
                        const float* __restrict__ emb) {
    size_t st = (size_t)gridDim.x * blockDim.x;
    for (size_t i = (size_t)blockIdx.x * blockDim.x + threadIdx.x;
         i < (size_t)Mm * Ee; i += st) {
        int r = (int)(i >> 9);
        int e = (int)(i & 511);
        int t = r >> 5, b = r & 31;
        float v;
        if (t == 0) v = feat[b * Ee + e];
        else        v = emb[(size_t)g_capIdx[b * Tt + t] * Ee + e];
        __half h, l; split16(v, h, l);
        g_XH[i] = h; g_XL[i] = l;
    }
}

// ---------------- split-fp16 wmma GEMM for Gx (validated round-8) -----------
__global__ __launch_bounds__(256)
void gemm_gx() {
    __shared__ __half sA[2][2][128 * 16];
    __shared__ __half sB[2][2][128 * 16];

    const __half *AH = g_XH, *AL = g_XL, *BH = g_WihH, *BL = g_WihL;

    int tid = threadIdx.x, wid = tid >> 5;
    int m0 = blockIdx.y * 128, n0 = blockIdx.x * 128;
    int wm = (wid >> 2) * 64, wn = (wid & 3) * 32;

    wmma::fragment<wmma::accumulator, 16, 16, 16, float> acc[4][2];
    #pragma unroll
    for (int mi = 0; mi < 4; mi++)
        #pragma unroll
        for (int ni = 0; ni < 2; ni++)
            wmma::load_matrix_sync(acc[mi][ni], g_bT0 + (n0 + wn + ni * 16),
                                   G4, wmma::mem_row_major);

    auto loadStage = [&](int ks, int st) {
        int kb = ks * 16;
        #pragma unroll
        for (int i = 0; i < 4; i++) {
            int c = i * 256 + tid;
            int cc = c & 255;
            int row = cc >> 1, q = cc & 1;
            const __half* gp; __half* sp;
            if (i == 0)      { gp = AH + (size_t)(m0 + row) * 512 + kb + q * 8;
                               sp = &sA[st][0][row * 16 + q * 8]; }
            else if (i == 1) { gp = AL + (size_t)(m0 + row) * 512 + kb + q * 8;
                               sp = &sA[st][1][row * 16 + q * 8]; }
            else if (i == 2) { gp = BH + (size_t)(n0 + row) * 512 + kb + q * 8;
                               sp = &sB[st][0][row * 16 + q * 8]; }
            else             { gp = BL + (size_t)(n0 + row) * 512 + kb + q * 8;
                               sp = &sB[st][1][row * 16 + q * 8]; }
            cpa16(sp, gp);
        }
    };

    loadStage(0, 0);
    asm volatile("cp.async.commit_group;\n");

    #pragma unroll 1
    for (int ks = 0; ks < 32; ks++) {
        if (ks < 31) {
            loadStage(ks + 1, (ks + 1) & 1);
            asm volatile("cp.async.commit_group;\n");
            asm volatile("cp.async.wait_group 1;\n");
        } else {
            asm volatile("cp.async.wait_group 0;\n");
        }
        __syncthreads();
        int st = ks & 1;

        wmma::fragment<wmma::matrix_b, 16, 16, 16, __half, wmma::col_major> fb[2], fbl[2];
        #pragma unroll
        for (int ni = 0; ni < 2; ni++) {
            wmma::load_matrix_sync(fb[ni],  &sB[st][0][(wn + ni * 16) * 16], 16);
            wmma::load_matrix_sync(fbl[ni], &sB[st][1][(wn + ni * 16) * 16], 16);
        }
        #pragma unroll
        for (int mi = 0; mi < 4; mi++) {
            wmma::fragment<wmma::matrix_a, 16, 16, 16, __half, wmma::row_major> fa, fal;
            wmma::load_matrix_sync(fa,  &sA[st][0][(wm + mi * 16) * 16], 16);
            wmma::load_matrix_sync(fal, &sA[st][1][(wm + mi * 16) * 16], 16);
            #pragma unroll
            for (int ni = 0; ni < 2; ni++) {
                wmma::mma_sync(acc[mi][ni], fa,  fb[ni],  acc[mi][ni]);
                wmma::mma_sync(acc[mi][ni], fa,  fbl[ni], acc[mi][ni]);
                wmma::mma_sync(acc[mi][ni], fal, fb[ni],  acc[mi][ni]);
            }
        }
        __syncthreads();
    }

    #pragma unroll
    for (int mi = 0; mi < 4; mi++)
        #pragma unroll
        for (int ni = 0; ni < 2; ni++)
            wmma::store_matrix_sync(
                g_GxT + (size_t)(n0 + wn + ni * 16) * Mm + (m0 + wm + mi * 16),
                acc[mi][ni], Mm, wmma::mem_col_major);
}

// ---------------- persistent LSTM recurrence (exact fp32, validated) --------
#define REC_CTAS 128

__global__ __launch_bounds__(256)
void lstm_kernel(const float* __restrict__ Whh) {
    __shared__ float2 sh2[8 * 16 * 32];   // 32 KB

    int tid = threadIdx.x, lane = tid & 31, w = tid >> 5;
    int n = blockIdx.x;
    int hf = n & 1;
    int ug = n >> 1;
    int u  = ug * 8 + w;
    int b  = hf * 16 + (lane & 15);

    unsigned long long w2[4][8];
    #pragma unroll
    for (int cc = 0; cc < 4; cc++) {
        const float2* wr = (const float2*)&Whh[(size_t)(cc * 512 + u) * 512];
        #pragma unroll
        for (int j = 0; j < 8; j++) {
            float2 v = wr[lane * 8 + j];
            w2[cc][j] = pk2(v.x, v.y);
        }
    }

    float cst = 0.f;

    for (int t = 0; t < 64; t++) {
        const float4* hc = (const float4*)g_h[t & 1];
        #pragma unroll
        for (int i = 0; i < 8; i++) {
            int q = i * 256 + tid;
            int bl = q >> 7;
            int k4 = q & 127;
            float4 v = __ldcg(hc + (size_t)(hf * 16 + bl) * 128 + k4);
            int k2a = 2 * k4, k2b = 2 * k4 + 1;
            sh2[((k2a & 7) * 16 + bl) * 32 + (k2a >> 3)] = make_float2(v.x, v.y);
            sh2[((k2b & 7) * 16 + bl) * 32 + (k2b >> 3)] = make_float2(v.z, v.w);
        }
        __syncthreads();

        unsigned long long a2[4][16];
        #pragma unroll
        for (int cc = 0; cc < 4; cc++)
            #pragma unroll
            for (int i = 0; i < 16; i++) a2[cc][i] = 0ull;

        #pragma unroll
        for (int j = 0; j < 8; j++) {
            #pragma unroll
            for (int bl = 0; bl < 16; bl++) {
                float2 hv = sh2[(j * 16 + bl) * 32 + lane];
                unsigned long long h2v = pk2(hv.x, hv.y);
                #pragma unroll
                for (int cc = 0; cc < 4; cc++)
                    a2[cc][bl] = ffma2(w2[cc][j], h2v, a2[cc][bl]);
            }
        }

        float gate[4];
        #pragma unroll
        for (int cc = 0; cc < 4; cc++) {
            float s[16];
            #pragma unroll
            for (int i = 0; i < 16; i++) {
                float x, y; upk2(a2[cc][i], x, y); s[i] = x + y;
            }
            int nb = 16;
            #pragma unroll
            for (int off = 8; off >= 1; off >>= 1) {
                int hn = nb >> 1;
                bool hi = (lane & off) != 0;
                #pragma unroll
                for (int i = 0; i < hn; i++) {
                    float give = hi ? s[i] : s[i + hn];
                    float keep = hi ? s[i + hn] : s[i];
                    float got  = __shfl_xor_sync(0xffffffffu, give, off);
                    s[i] = keep + got;
                }
                nb = hn;
            }
            s[0] += __shfl_xor_sync(0xffffffffu, s[0], 16);
            gate[cc] = s[0];
        }

        int row = t * 32 + b;
        #pragma unroll
        for (int cc = 0; cc < 4; cc++)
            gate[cc] += __ldg(&g_GxT[(size_t)(cc * 512 + u) * Mm + row]);

        float ig = 1.f / (1.f + expf(-gate[0]));
        float fg = 1.f / (1.f + expf(-gate[1]));
        float gg = tanhf(gate[2]);
        float og = 1.f / (1.f + expf(-gate[3]));
        cst = fg * cst + ig * gg;
        float hN = og * tanhf(cst);

        if (lane < 16) {
            g_h[(t + 1) & 1][b * 512 + u] = hN;
            int rr = b * 64 + t;
            __half hh, hl; split16(hN, hh, hl);
            g_hsH[(size_t)rr * 512 + u] = hh;
            g_hsL[(size_t)rr * 512 + u] = hl;
        }

        __threadfence();
        __syncthreads();
        if (tid == 0) {
            atomicAdd(&g_bcount, 1u);
            unsigned tgt = (unsigned)REC_CTAS * (unsigned)(t + 1);
            while (*(volatile unsigned*)&g_bcount < tgt) { __nanosleep(32); }
            __threadfence();
        }
        __syncthreads();
    }
}

// ---------------- V-GEMM: split-fp16 wmma, BK=32, 1 sync/iter ---------------
// out[rr][v] = sum_k hs[rr][k]*Wout[v][k] + b_out[v].
// smem: 2 stages x 4 matrices (AH,AL,BH,BL) x 2 k16-slabs x (128x16) halves
//       = 64 KB dynamic; reused as 128x128 f32 tile for the coalesced epilogue.
#define VSMEM (64 * 1024)
__device__ __forceinline__ int vslab(int st, int mtx, int ks2) {
    return ((st * 4 + mtx) * 2 + ks2) * 2048;   // in __half units
}

__global__ __launch_bounds__(256)
void gemm_v(const float* __restrict__ b_out, float* __restrict__ out) {
    extern __shared__ __half vsm[];

    int tid = threadIdx.x, wid = tid >> 5;
    int n0 = blockIdx.x * 128, m0 = blockIdx.y * 128;
    int wm = (wid >> 2) * 64, wn = (wid & 3) * 32;

    wmma::fragment<wmma::accumulator, 16, 16, 16, float> acc[4][2];
    #pragma unroll
    for (int mi = 0; mi < 4; mi++)
        #pragma unroll
        for (int ni = 0; ni < 2; ni++)
            wmma::fill_fragment(acc[mi][ni], 0.f);

    const __half* gmat[4] = { g_hsH, g_hsL, g_WoutH, g_WoutL };

    auto loadStage = [&](int kc, int st) {
        #pragma unroll
        for (int i = 0; i < 8; i++) {
            int c    = i * 256 + tid;        // 0..2047
            int mtx  = c >> 9;
            int cc   = c & 511;
            int ks2  = cc >> 8;
            int ccc  = cc & 255;
            int row  = ccc >> 1, q = ccc & 1;
            int rbase = (mtx < 2) ? m0 : n0;
            cpa16(&vsm[vslab(st, mtx, ks2) + row * 16 + q * 8],
                  gmat[mtx] + (size_t)(rbase + row) * 512 + kc * 32 + ks2 * 16 + q * 8);
        }
        asm volatile("cp.async.commit_group;\n");
    };

    loadStage(0, 0);

    #pragma unroll 1
    for (int kc = 0; kc < 16; kc++) {
        int st = kc & 1;
        asm volatile("cp.async.wait_group 0;\n");
        __syncthreads();                         // stage st ready; st^1 free
        if (kc < 15) loadStage(kc + 1, st ^ 1);  // overlaps compute below

        #pragma unroll
        for (int ks2 = 0; ks2 < 2; ks2++) {
            wmma::fragment<wmma::matrix_b, 16, 16, 16, __half, wmma::col_major> fb[2], fbl[2];
            #pragma unroll
            for (int ni = 0; ni < 2; ni++) {
                wmma::load_matrix_sync(fb[ni],
                    &vsm[vslab(st, 2, ks2) + (wn + ni * 16) * 16], 16);
                wmma::load_matrix_sync(fbl[ni],
                    &vsm[vslab(st, 3, ks2) + (wn + ni * 16) * 16], 16);
            }
            #pragma unroll
            for (int mi = 0; mi < 4; mi++) {
                wmma::fragment<wmma::matrix_a, 16, 16, 16, __half, wmma::row_major> fa, fal;
                wmma::load_matrix_sync(fa,
                    &vsm[vslab(st, 0, ks2) + (wm + mi * 16) * 16], 16);
                wmma::load_matrix_sync(fal,
                    &vsm[vslab(st, 1, ks2) + (wm + mi * 16) * 16], 16);
                #pragma unroll
                for (int ni = 0; ni < 2; ni++) {
                    wmma::mma_sync(acc[mi][ni], fa,  fb[ni],  acc[mi][ni]);
                    wmma::mma_sync(acc[mi][ni], fa,  fbl[ni], acc[mi][ni]);
                    wmma::mma_sync(acc[mi][ni], fal, fb[ni],  acc[mi][ni]);
                }
            }
        }
    }

    // coalesced epilogue: stage the 128x128 f32 tile in smem, then float4 out
    __syncthreads();
    float* ct = (float*)vsm;
    #pragma unroll
    for (int mi = 0; mi < 4; mi++)
        #pragma unroll
        for (int ni = 0; ni < 2; ni++)
            wmma::store_matrix_sync(ct + (wm + mi * 16) * 128 + (wn + ni * 16),
                                    acc[mi][ni], 128, wmma::mem_row_major);
    __syncthreads();

    #pragma unroll
    for (int it = 0; it < 16; it++) {
        int f   = it * 256 + tid;        // 0..4095 float4s
        int row = f >> 5, c4 = f & 31;
        const float4* src = (const float4*)(ct + row * 128) + c4;
        float4 v = *src;
        const float4 bv = *((const float4*)(b_out + n0) + c4);
        v.x += bv.x; v.y += bv.y; v.z += bv.z; v.w += bv.w;
        *((float4*)(out + (size_t)(m0 + row) * Vv + n0) + c4) = v;
    }
}

// ---------------- launch -----------------------------------------------------
extern "C" void kernel_launch(void* const* d_in, const int* in_sizes, int n_in,
                              void* d_out, int out_size) {
    const float* feat  = (const float*)d_in[0];
    const int*   cap32 = (const int*)d_in[1];
    const float* W_ih  = (const float*)d_in[2];
    const float* W_hh  = (const float*)d_in[3];
    const float* b_ih  = (const float*)d_in[4];
    const float* b_hh  = (const float*)d_in[5];
    const float* W_out = (const float*)d_in[6];
    const float* b_out = (const float*)d_in[7];
    const float* emb   = (const float*)d_in[8];
    float* out = (float*)d_out;

    cudaFuncSetAttribute(gemm_v, cudaFuncAttributeMaxDynamicSharedMemorySize,
                         VSMEM);

    prep_misc<<<64, 256>>>(cap32, b_ih, b_hh);
    conv_weights<<<2048, 256>>>(W_ih, W_out);
    build_x<<<512, 256>>>(feat, emb);
    gemm_gx<<<dim3(G4 / 128, Mm / 128), 256>>>();
    lstm_kernel<<<REC_CTAS, 256>>>(W_hh);
    gemm_v<<<dim3(Vv / 128, Mm / 128), 256, VSMEM>>>(b_out, out);
}

// round 13
// speedup vs baseline: 1.0815x; 1.0522x over previous
#include <cuda_runtime.h>
#include <cuda_fp16.h>
#include <mma.h>
#include <cstdint>
#include <cstddef>
using namespace nvcuda;

#define Bb 32
#define Tt 64
#define Ee 512
#define Hh 512
#define Vv 32000
#define G4 2048
#define Mm 2048   // T*B rows; Gx rows r = t*32+b; V-GEMM A rows rr = b*64+t

// ---------------- static device scratch (no allocations allowed) -----------
__device__ __half g_XH[Mm * Ee];
__device__ __half g_XL[Mm * Ee];
__device__ __half g_WihH[G4 * Ee];
__device__ __half g_WihL[G4 * Ee];
__device__ __half g_WoutH[(size_t)Vv * Hh];
__device__ __half g_WoutL[(size_t)Vv * Hh];
__device__ __half g_hsH[Mm * Hh];           // split h history, rows rr=b*64+t
__device__ __half g_hsL[Mm * Hh];
__device__ float  g_GxT[(size_t)G4 * Mm];   // [gatecol][row r=t*32+b]
__device__ float  g_h[2][Bb * Hh];          // ping-pong recurrent h
__device__ float  g_bT0[16 * G4];           // replicated bias tile b_ih+b_hh
__device__ int    g_capIdx[Bb * Tt];        // decoded caption token indices
__device__ unsigned g_bcount;               // grid barrier counter

// ---------------- helpers ---------------------------------------------------
__device__ __forceinline__ unsigned long long pk2(float x, float y) {
    unsigned long long r; asm("mov.b64 %0, {%1, %2};" : "=l"(r) : "f"(x), "f"(y));
    return r;
}
__device__ __forceinline__ void upk2(unsigned long long a, float& x, float& y) {
    asm("mov.b64 {%0, %1}, %2;" : "=f"(x), "=f"(y) : "l"(a));
}
__device__ __forceinline__ unsigned long long ffma2(unsigned long long a,
                                                    unsigned long long b,
                                                    unsigned long long c) {
    unsigned long long d;
    asm("fma.rn.f32x2 %0, %1, %2, %3;" : "=l"(d) : "l"(a), "l"(b), "l"(c));
    return d;
}
__device__ __forceinline__ unsigned smaddr(const void* p) {
    return (unsigned)__cvta_generic_to_shared(p);
}
__device__ __forceinline__ void cpa16(void* s, const void* g) {
    asm volatile("cp.async.cg.shared.global [%0], [%1], 16;\n"
                 :: "r"(smaddr(s)), "l"(g));
}
__device__ __forceinline__ void split16(float v, __half& hi, __half& lo) {
    hi = __float2half_rn(v);
    lo = __float2half_rn(v - __half2float(hi));
}

// ---------------- fused small prep ------------------------------------------
__global__ void prep_misc(const int* __restrict__ cap32,
                          const float* __restrict__ b_ih,
                          const float* __restrict__ b_hh) {
    if (blockIdx.x == 0) {
        __shared__ int anyOdd;
        if (threadIdx.x == 0) { anyOdd = 0; g_bcount = 0u; }
        __syncthreads();
        int local = 0;
        for (int i = threadIdx.x; i < (Bb * Tt) / 2; i += blockDim.x)
            local |= cap32[2 * i + 1];
        if (local) atomicOr(&anyOdd, 1);
        __syncthreads();
        bool is64 = (anyOdd == 0);
        for (int i = threadIdx.x; i < Bb * Tt; i += blockDim.x) {
            int idx = is64 ? cap32[2 * i] : cap32[i];
            idx = idx < 0 ? 0 : (idx >= Vv ? Vv - 1 : idx);
            g_capIdx[i] = idx;
        }
        for (int i = threadIdx.x; i < Bb * Hh; i += blockDim.x) g_h[0][i] = 0.f;
    }
    size_t st = (size_t)gridDim.x * blockDim.x;
    for (size_t i = (size_t)blockIdx.x * blockDim.x + threadIdx.x;
         i < (size_t)16 * G4; i += st) {
        int j = (int)(i & 2047);
        g_bT0[i] = b_ih[j] + b_hh[j];
    }
}

// ---------------- fused weight conversion ------------------------------------
__global__ void conv_weights(const float* __restrict__ W_ih,
                             const float* __restrict__ W_out) {
    const size_t n1 = (size_t)G4 * Ee;
    const size_t n2 = (size_t)Vv * Hh;
    size_t st = (size_t)gridDim.x * blockDim.x;
    for (size_t i = (size_t)blockIdx.x * blockDim.x + threadIdx.x;
         i < n1 + n2; i += st) {
        if (i < n1) {
            __half h, l; split16(W_ih[i], h, l);
            g_WihH[i] = h; g_WihL[i] = l;
        } else {
            size_t j = i - n1;
            __half h, l; split16(W_out[j], h, l);
            g_WoutH[j] = h; g_WoutL[j] = l;
        }
    }
}

__global__ void build_x(const float* __restrict__ feat,
                        const float* __restrict__ emb) {
    size_t st = (size_t)gridDim.x * blockDim.x;
    for (size_t i = (size_t)blockIdx.x * blockDim.x + threadIdx.x;
         i < (size_t)Mm * Ee; i += st) {
        int r = (int)(i >> 9);
        int e = (int)(i & 511);
        int t = r >> 5, b = r & 31;
        float v;
        if (t == 0) v = feat[b * Ee + e];
        else        v = emb[(size_t)g_capIdx[b * Tt + t] * Ee + e];
        __half h, l; split16(v, h, l);
        g_XH[i] = h; g_XL[i] = l;
    }
}

// ---------------- split-fp16 wmma GEMM for Gx (validated round-8) -----------
__global__ __launch_bounds__(256)
void gemm_gx() {
    __shared__ __half sA[2][2][128 * 16];
    __shared__ __half sB[2][2][128 * 16];

    const __half *AH = g_XH, *AL = g_XL, *BH = g_WihH, *BL = g_WihL;

    int tid = threadIdx.x, wid = tid >> 5;
    int m0 = blockIdx.y * 128, n0 = blockIdx.x * 128;
    int wm = (wid >> 2) * 64, wn = (wid & 3) * 32;

    wmma::fragment<wmma::accumulator, 16, 16, 16, float> acc[4][2];
    #pragma unroll
    for (int mi = 0; mi < 4; mi++)
        #pragma unroll
        for (int ni = 0; ni < 2; ni++)
            wmma::load_matrix_sync(acc[mi][ni], g_bT0 + (n0 + wn + ni * 16),
                                   G4, wmma::mem_row_major);

    auto loadStage = [&](int ks, int st) {
        int kb = ks * 16;
        #pragma unroll
        for (int i = 0; i < 4; i++) {
            int c = i * 256 + tid;
            int cc = c & 255;
            int row = cc >> 1, q = cc & 1;
            const __half* gp; __half* sp;
            if (i == 0)      { gp = AH + (size_t)(m0 + row) * 512 + kb + q * 8;
                               sp = &sA[st][0][row * 16 + q * 8]; }
            else if (i == 1) { gp = AL + (size_t)(m0 + row) * 512 + kb + q * 8;
                               sp = &sA[st][1][row * 16 + q * 8]; }
            else if (i == 2) { gp = BH + (size_t)(n0 + row) * 512 + kb + q * 8;
                               sp = &sB[st][0][row * 16 + q * 8]; }
            else             { gp = BL + (size_t)(n0 + row) * 512 + kb + q * 8;
                               sp = &sB[st][1][row * 16 + q * 8]; }
            cpa16(sp, gp);
        }
    };

    loadStage(0, 0);
    asm volatile("cp.async.commit_group;\n");

    #pragma unroll 1
    for (int ks = 0; ks < 32; ks++) {
        if (ks < 31) {
            loadStage(ks + 1, (ks + 1) & 1);
            asm volatile("cp.async.commit_group;\n");
            asm volatile("cp.async.wait_group 1;\n");
        } else {
            asm volatile("cp.async.wait_group 0;\n");
        }
        __syncthreads();
        int st = ks & 1;

        wmma::fragment<wmma::matrix_b, 16, 16, 16, __half, wmma::col_major> fb[2], fbl[2];
        #pragma unroll
        for (int ni = 0; ni < 2; ni++) {
            wmma::load_matrix_sync(fb[ni],  &sB[st][0][(wn + ni * 16) * 16], 16);
            wmma::load_matrix_sync(fbl[ni], &sB[st][1][(wn + ni * 16) * 16], 16);
        }
        #pragma unroll
        for (int mi = 0; mi < 4; mi++) {
            wmma::fragment<wmma::matrix_a, 16, 16, 16, __half, wmma::row_major> fa, fal;
            wmma::load_matrix_sync(fa,  &sA[st][0][(wm + mi * 16) * 16], 16);
            wmma::load_matrix_sync(fal, &sA[st][1][(wm + mi * 16) * 16], 16);
            #pragma unroll
            for (int ni = 0; ni < 2; ni++) {
                wmma::mma_sync(acc[mi][ni], fa,  fb[ni],  acc[mi][ni]);
                wmma::mma_sync(acc[mi][ni], fa,  fbl[ni], acc[mi][ni]);
                wmma::mma_sync(acc[mi][ni], fal, fb[ni],  acc[mi][ni]);
            }
        }
        __syncthreads();
    }

    #pragma unroll
    for (int mi = 0; mi < 4; mi++)
        #pragma unroll
        for (int ni = 0; ni < 2; ni++)
            wmma::store_matrix_sync(
                g_GxT + (size_t)(n0 + wn + ni * 16) * Mm + (m0 + wm + mi * 16),
                acc[mi][ni], Mm, wmma::mem_col_major);
}

// ---------------- persistent LSTM recurrence (exact fp32, validated) --------
#define REC_CTAS 128

__global__ __launch_bounds__(256)
void lstm_kernel(const float* __restrict__ Whh) {
    __shared__ float2 sh2[8 * 16 * 32];   // 32 KB

    int tid = threadIdx.x, lane = tid & 31, w = tid >> 5;
    int n = blockIdx.x;
    int hf = n & 1;
    int ug = n >> 1;
    int u  = ug * 8 + w;
    int b  = hf * 16 + (lane & 15);

    unsigned long long w2[4][8];
    #pragma unroll
    for (int cc = 0; cc < 4; cc++) {
        const float2* wr = (const float2*)&Whh[(size_t)(cc * 512 + u) * 512];
        #pragma unroll
        for (int j = 0; j < 8; j++) {
            float2 v = wr[lane * 8 + j];
            w2[cc][j] = pk2(v.x, v.y);
        }
    }

    float cst = 0.f;

    for (int t = 0; t < 64; t++) {
        const float4* hc = (const float4*)g_h[t & 1];
        #pragma unroll
        for (int i = 0; i < 8; i++) {
            int q = i * 256 + tid;
            int bl = q >> 7;
            int k4 = q & 127;
            float4 v = __ldcg(hc + (size_t)(hf * 16 + bl) * 128 + k4);
            int k2a = 2 * k4, k2b = 2 * k4 + 1;
            sh2[((k2a & 7) * 16 + bl) * 32 + (k2a >> 3)] = make_float2(v.x, v.y);
            sh2[((k2b & 7) * 16 + bl) * 32 + (k2b >> 3)] = make_float2(v.z, v.w);
        }
        __syncthreads();

        unsigned long long a2[4][16];
        #pragma unroll
        for (int cc = 0; cc < 4; cc++)
            #pragma unroll
            for (int i = 0; i < 16; i++) a2[cc][i] = 0ull;

        #pragma unroll
        for (int j = 0; j < 8; j++) {
            #pragma unroll
            for (int bl = 0; bl < 16; bl++) {
                float2 hv = sh2[(j * 16 + bl) * 32 + lane];
                unsigned long long h2v = pk2(hv.x, hv.y);
                #pragma unroll
                for (int cc = 0; cc < 4; cc++)
                    a2[cc][bl] = ffma2(w2[cc][j], h2v, a2[cc][bl]);
            }
        }

        float gate[4];
        #pragma unroll
        for (int cc = 0; cc < 4; cc++) {
            float s[16];
            #pragma unroll
            for (int i = 0; i < 16; i++) {
                float x, y; upk2(a2[cc][i], x, y); s[i] = x + y;
            }
            int nb = 16;
            #pragma unroll
            for (int off = 8; off >= 1; off >>= 1) {
                int hn = nb >> 1;
                bool hi = (lane & off) != 0;
                #pragma unroll
                for (int i = 0; i < hn; i++) {
                    float give = hi ? s[i] : s[i + hn];
                    float keep = hi ? s[i + hn] : s[i];
                    float got  = __shfl_xor_sync(0xffffffffu, give, off);
                    s[i] = keep + got;
                }
                nb = hn;
            }
            s[0] += __shfl_xor_sync(0xffffffffu, s[0], 16);
            gate[cc] = s[0];
        }

        int row = t * 32 + b;
        #pragma unroll
        for (int cc = 0; cc < 4; cc++)
            gate[cc] += __ldg(&g_GxT[(size_t)(cc * 512 + u) * Mm + row]);

        float ig = 1.f / (1.f + expf(-gate[0]));
        float fg = 1.f / (1.f + expf(-gate[1]));
        float gg = tanhf(gate[2]);
        float og = 1.f / (1.f + expf(-gate[3]));
        cst = fg * cst + ig * gg;
        float hN = og * tanhf(cst);

        if (lane < 16) {
            g_h[(t + 1) & 1][b * 512 + u] = hN;
            int rr = b * 64 + t;
            __half hh, hl; split16(hN, hh, hl);
            g_hsH[(size_t)rr * 512 + u] = hh;
            g_hsL[(size_t)rr * 512 + u] = hl;
        }

        __threadfence();
        __syncthreads();
        if (tid == 0) {
            atomicAdd(&g_bcount, 1u);
            unsigned tgt = (unsigned)REC_CTAS * (unsigned)(t + 1);
            while (*(volatile unsigned*)&g_bcount < tgt) { __nanosleep(32); }
            __threadfence();
        }
        __syncthreads();
    }
}

// ---------------- V-GEMM: split-fp16 wmma, padded smem (conflict-free) ------
// out[rr][v] = sum_k hs[rr][k]*Wout[v][k] + b_out[v].
// Operand tiles 128x32 halves padded to row stride 40 (80B): ldmatrix rows hit
// banks (r*20)%32 = {0,20,8,28,16,4,24,12} -> conflict-free fragment loads.
// smem: 2 stages x 4 matrices x 128x40 halves = 80 KB; reused as 128x132 f32
// padded tile for the coalesced epilogue.
#define VST   40
#define VSMEM (2 * 4 * 128 * VST * 2)       // 81920 B
#define EPI_LD 132

__device__ __forceinline__ int vslab(int st, int mtx) {
    return (st * 4 + mtx) * (128 * VST);    // in __half units
}

__global__ __launch_bounds__(256)
void gemm_v(const float* __restrict__ b_out, float* __restrict__ out) {
    extern __shared__ __half vsm[];

    int tid = threadIdx.x, wid = tid >> 5;
    int n0 = blockIdx.x * 128, m0 = blockIdx.y * 128;
    int wm = (wid >> 2) * 64, wn = (wid & 3) * 32;

    wmma::fragment<wmma::accumulator, 16, 16, 16, float> acc[4][2];
    #pragma unroll
    for (int mi = 0; mi < 4; mi++)
        #pragma unroll
        for (int ni = 0; ni < 2; ni++)
            wmma::fill_fragment(acc[mi][ni], 0.f);

    const __half* gmat[4] = { g_hsH, g_hsL, g_WoutH, g_WoutL };

    // 4 matrices x 128 rows x 4 16B-chunks = 2048 cp.asyncs per stage
    auto loadStage = [&](int kc, int st) {
        #pragma unroll
        for (int i = 0; i < 8; i++) {
            int c   = i * 256 + tid;        // 0..2047
            int mtx = c >> 9;
            int cc  = c & 511;
            int row = cc >> 2, q = cc & 3;
            int rbase = (mtx < 2) ? m0 : n0;
            cpa16(&vsm[vslab(st, mtx) + row * VST + q * 8],
                  gmat[mtx] + (size_t)(rbase + row) * 512 + kc * 32 + q * 8);
        }
        asm volatile("cp.async.commit_group;\n");
    };

    loadStage(0, 0);

    #pragma unroll 1
    for (int kc = 0; kc < 16; kc++) {
        int st = kc & 1;
        asm volatile("cp.async.wait_group 0;\n");
        __syncthreads();                         // stage st ready; st^1 free
        if (kc < 15) loadStage(kc + 1, st ^ 1);  // overlaps compute below

        #pragma unroll
        for (int ks2 = 0; ks2 < 2; ks2++) {
            int ko = ks2 * 16;
            wmma::fragment<wmma::matrix_b, 16, 16, 16, __half, wmma::col_major> fb[2], fbl[2];
            #pragma unroll
            for (int ni = 0; ni < 2; ni++) {
                wmma::load_matrix_sync(fb[ni],
                    &vsm[vslab(st, 2) + (wn + ni * 16) * VST + ko], VST);
                wmma::load_matrix_sync(fbl[ni],
                    &vsm[vslab(st, 3) + (wn + ni * 16) * VST + ko], VST);
            }
            #pragma unroll
            for (int mi = 0; mi < 4; mi++) {
                wmma::fragment<wmma::matrix_a, 16, 16, 16, __half, wmma::row_major> fa, fal;
                wmma::load_matrix_sync(fa,
                    &vsm[vslab(st, 0) + (wm + mi * 16) * VST + ko], VST);
                wmma::load_matrix_sync(fal,
                    &vsm[vslab(st, 1) + (wm + mi * 16) * VST + ko], VST);
                #pragma unroll
                for (int ni = 0; ni < 2; ni++) {
                    wmma::mma_sync(acc[mi][ni], fa,  fb[ni],  acc[mi][ni]);
                    wmma::mma_sync(acc[mi][ni], fa,  fbl[ni], acc[mi][ni]);
                    wmma::mma_sync(acc[mi][ni], fal, fb[ni],  acc[mi][ni]);
                }
            }
        }
    }

    // coalesced epilogue: stage padded 128x132 f32 tile, then float4 stores
    __syncthreads();
    float* ct = (float*)vsm;
    #pragma unroll
    for (int mi = 0; mi < 4; mi++)
        #pragma unroll
        for (int ni = 0; ni < 2; ni++)
            wmma::store_matrix_sync(ct + (wm + mi * 16) * EPI_LD + (wn + ni * 16),
                                    acc[mi][ni], EPI_LD, wmma::mem_row_major);
    __syncthreads();

    #pragma unroll
    for (int it = 0; it < 16; it++) {
        int f   = it * 256 + tid;        // 0..4095 float4s
        int row = f >> 5, c4 = f & 31;
        const float* sp = ct + row * EPI_LD + c4 * 4;
        float4 v = make_float4(sp[0], sp[1], sp[2], sp[3]);
        const float4 bv = *((const float4*)(b_out + n0) + c4);
        v.x += bv.x; v.y += bv.y; v.z += bv.z; v.w += bv.w;
        *((float4*)(out + (size_t)(m0 + row) * Vv + n0) + c4) = v;
    }
}

// ---------------- launch -----------------------------------------------------
extern "C" void kernel_launch(void* const* d_in, const int* in_sizes, int n_in,
                              void* d_out, int out_size) {
    const float* feat  = (const float*)d_in[0];
    const int*   cap32 = (const int*)d_in[1];
    const float* W_ih  = (const float*)d_in[2];
    const float* W_hh  = (const float*)d_in[3];
    const float* b_ih  = (const float*)d_in[4];
    const float* b_hh  = (const float*)d_in[5];
    const float* W_out = (const float*)d_in[6];
    const float* b_out = (const float*)d_in[7];
    const float* emb   = (const float*)d_in[8];
    float* out = (float*)d_out;

    cudaFuncSetAttribute(gemm_v, cudaFuncAttributeMaxDynamicSharedMemorySize,
                         VSMEM);

    prep_misc<<<64, 256>>>(cap32, b_ih, b_hh);
    conv_weights<<<2048, 256>>>(W_ih, W_out);
    build_x<<<512, 256>>>(feat, emb);
    gemm_gx<<<dim3(G4 / 128, Mm / 128), 256>>>();
    lstm_kernel<<<REC_CTAS, 256>>>(W_hh);
    gemm_v<<<dim3(Vv / 128, Mm / 128), 256, VSMEM>>>(b_out, out);
}

// round 17
// speedup vs baseline: 1.5593x; 1.4418x over previous
#include <cuda_runtime.h>
#include <cuda_fp16.h>
#include <mma.h>
#include <cstdint>
#include <cstddef>
using namespace nvcuda;

#define Bb 32
#define Tt 64
#define Ee 512
#define Hh 512
#define Vv 32000
#define G4 2048
#define Mm 2048   // T*B rows; Gx rows r = t*32+b; V-GEMM A rows rr = b*64+t

// ---------------- static device scratch (no allocations allowed) -----------
__device__ __half g_XH[Mm * Ee];
__device__ __half g_XL[Mm * Ee];
__device__ __half g_WihH[G4 * Ee];
__device__ __half g_WihL[G4 * Ee];
__device__ __half g_WoutH[(size_t)Vv * Hh];   // plain fp16 W_out
__device__ __half g_hsH[Mm * Hh];             // fp16 h history, rows rr=b*64+t
__device__ float  g_GxT[(size_t)G4 * Mm];     // [gatecol][row r=t*32+b]
__device__ float  g_h[2][Bb * Hh];            // ping-pong recurrent h
__device__ float  g_bT0[16 * G4];             // replicated bias tile b_ih+b_hh
__device__ int    g_capIdx[Bb * Tt];          // decoded caption token indices
__device__ unsigned g_bcount;                 // grid barrier counter

// ---------------- helpers ---------------------------------------------------
__device__ __forceinline__ unsigned long long pk2(float x, float y) {
    unsigned long long r; asm("mov.b64 %0, {%1, %2};" : "=l"(r) : "f"(x), "f"(y));
    return r;
}
__device__ __forceinline__ void upk2(unsigned long long a, float& x, float& y) {
    asm("mov.b64 {%0, %1}, %2;" : "=f"(x), "=f"(y) : "l"(a));
}
__device__ __forceinline__ unsigned long long ffma2(unsigned long long a,
                                                    unsigned long long b,
                                                    unsigned long long c) {
    unsigned long long d;
    asm("fma.rn.f32x2 %0, %1, %2, %3;" : "=l"(d) : "l"(a), "l"(b), "l"(c));
    return d;
}
__device__ __forceinline__ unsigned smaddr(const void* p) {
    return (unsigned)__cvta_generic_to_shared(p);
}
__device__ __forceinline__ void cpa16(void* s, const void* g) {
    asm volatile("cp.async.cg.shared.global [%0], [%1], 16;\n"
                 :: "r"(smaddr(s)), "l"(g));
}
__device__ __forceinline__ void split16(float v, __half& hi, __half& lo) {
    hi = __float2half_rn(v);
    lo = __float2half_rn(v - __half2float(hi));
}

// ---------------- fused small prep ------------------------------------------
__global__ void prep_misc(const int* __restrict__ cap32,
                          const float* __restrict__ b_ih,
                          const float* __restrict__ b_hh) {
    if (blockIdx.x == 0) {
        __shared__ int anyOdd;
        if (threadIdx.x == 0) { anyOdd = 0; g_bcount = 0u; }
        __syncthreads();
        int local = 0;
        for (int i = threadIdx.x; i < (Bb * Tt) / 2; i += blockDim.x)
            local |= cap32[2 * i + 1];
        if (local) atomicOr(&anyOdd, 1);
        __syncthreads();
        bool is64 = (anyOdd == 0);
        for (int i = threadIdx.x; i < Bb * Tt; i += blockDim.x) {
            int idx = is64 ? cap32[2 * i] : cap32[i];
            idx = idx < 0 ? 0 : (idx >= Vv ? Vv - 1 : idx);
            g_capIdx[i] = idx;
        }
        for (int i = threadIdx.x; i < Bb * Hh; i += blockDim.x) g_h[0][i] = 0.f;
    }
    size_t st = (size_t)gridDim.x * blockDim.x;
    for (size_t i = (size_t)blockIdx.x * blockDim.x + threadIdx.x;
         i < (size_t)16 * G4; i += st) {
        int j = (int)(i & 2047);
        g_bT0[i] = b_ih[j] + b_hh[j];
    }
}

// ---------------- fused weight conversion ------------------------------------
__global__ void conv_weights(const float* __restrict__ W_ih,
                             const float* __restrict__ W_out) {
    const size_t n1 = (size_t)G4 * Ee;
    const size_t n2 = (size_t)Vv * Hh;
    size_t st = (size_t)gridDim.x * blockDim.x;
    for (size_t i = (size_t)blockIdx.x * blockDim.x + threadIdx.x;
         i < n1 + n2; i += st) {
        if (i < n1) {
            __half h, l; split16(W_ih[i], h, l);
            g_WihH[i] = h; g_WihL[i] = l;
        } else {
            size_t j = i - n1;
            g_WoutH[j] = __float2half_rn(W_out[j]);
        }
    }
}

__global__ void build_x(const float* __restrict__ feat,
                        const float* __restrict__ emb) {
    size_t st = (size_t)gridDim.x * blockDim.x;
    for (size_t i = (size_t)blockIdx.x * blockDim.x + threadIdx.x;
         i < (size_t)Mm * Ee; i += st) {
        int r = (int)(i >> 9);
        int e = (int)(i & 511);
        int t = r >> 5, b = r & 31;
        float v;
        if (t == 0) v = feat[b * Ee + e];
        else        v = emb[(size_t)g_capIdx[b * Tt + t] * Ee + e];
        __half h, l; split16(v, h, l);
        g_XH[i] = h; g_XL[i] = l;
    }
}

// ---------------- split-fp16 wmma GEMM for Gx (validated, unchanged) --------
__global__ __launch_bounds__(256)
void gemm_gx() {
    __shared__ __half sA[2][2][128 * 16];
    __shared__ __half sB[2][2][128 * 16];

    const __half *AH = g_XH, *AL = g_XL, *BH = g_WihH, *BL = g_WihL;

    int tid = threadIdx.x, wid = tid >> 5;
    int m0 = blockIdx.y * 128, n0 = blockIdx.x * 128;
    int wm = (wid >> 2) * 64, wn = (wid & 3) * 32;

    wmma::fragment<wmma::accumulator, 16, 16, 16, float> acc[4][2];
    #pragma unroll
    for (int mi = 0; mi < 4; mi++)
        #pragma unroll
        for (int ni = 0; ni < 2; ni++)
            wmma::load_matrix_sync(acc[mi][ni], g_bT0 + (n0 + wn + ni * 16),
                                   G4, wmma::mem_row_major);

    auto loadStage = [&](int ks, int st) {
        int kb = ks * 16;
        #pragma unroll
        for (int i = 0; i < 4; i++) {
            int c = i * 256 + tid;
            int cc = c & 255;
            int row = cc >> 1, q = cc & 1;
            const __half* gp; __half* sp;
            if (i == 0)      { gp = AH + (size_t)(m0 + row) * 512 + kb + q * 8;
                               sp = &sA[st][0][row * 16 + q * 8]; }
            else if (i == 1) { gp = AL + (size_t)(m0 + row) * 512 + kb + q * 8;
                               sp = &sA[st][1][row * 16 + q * 8]; }
            else if (i == 2) { gp = BH + (size_t)(n0 + row) * 512 + kb + q * 8;
                               sp = &sB[st][0][row * 16 + q * 8]; }
            else             { gp = BL + (size_t)(n0 + row) * 512 + kb + q * 8;
                               sp = &sB[st][1][row * 16 + q * 8]; }
            cpa16(sp, gp);
        }
    };

    loadStage(0, 0);
    asm volatile("cp.async.commit_group;\n");

    #pragma unroll 1
    for (int ks = 0; ks < 32; ks++) {
        if (ks < 31) {
            loadStage(ks + 1, (ks + 1) & 1);
            asm volatile("cp.async.commit_group;\n");
            asm volatile("cp.async.wait_group 1;\n");
        } else {
            asm volatile("cp.async.wait_group 0;\n");
        }
        __syncthreads();
        int st = ks & 1;

        wmma::fragment<wmma::matrix_b, 16, 16, 16, __half, wmma::col_major> fb[2], fbl[2];
        #pragma unroll
        for (int ni = 0; ni < 2; ni++) {
            wmma::load_matrix_sync(fb[ni],  &sB[st][0][(wn + ni * 16) * 16], 16);
            wmma::load_matrix_sync(fbl[ni], &sB[st][1][(wn + ni * 16) * 16], 16);
        }
        #pragma unroll
        for (int mi = 0; mi < 4; mi++) {
            wmma::fragment<wmma::matrix_a, 16, 16, 16, __half, wmma::row_major> fa, fal;
            wmma::load_matrix_sync(fa,  &sA[st][0][(wm + mi * 16) * 16], 16);
            wmma::load_matrix_sync(fal, &sA[st][1][(wm + mi * 16) * 16], 16);
            #pragma unroll
            for (int ni = 0; ni < 2; ni++) {
                wmma::mma_sync(acc[mi][ni], fa,  fb[ni],  acc[mi][ni]);
                wmma::mma_sync(acc[mi][ni], fa,  fbl[ni], acc[mi][ni]);
                wmma::mma_sync(acc[mi][ni], fal, fb[ni],  acc[mi][ni]);
            }
        }
        __syncthreads();
    }

    #pragma unroll
    for (int mi = 0; mi < 4; mi++)
        #pragma unroll
        for (int ni = 0; ni < 2; ni++)
            wmma::store_matrix_sync(
                g_GxT + (size_t)(n0 + wn + ni * 16) * Mm + (m0 + wm + mi * 16),
                acc[mi][ni], Mm, wmma::mem_col_major);
}

// ---------------- persistent LSTM recurrence (exact fp32, validated) --------
#define REC_CTAS 128

__global__ __launch_bounds__(256)
void lstm_kernel(const float* __restrict__ Whh) {
    __shared__ float2 sh2[8 * 16 * 32];   // 32 KB

    int tid = threadIdx.x, lane = tid & 31, w = tid >> 5;
    int n = blockIdx.x;
    int hf = n & 1;
    int ug = n >> 1;
    int u  = ug * 8 + w;
    int b  = hf * 16 + (lane & 15);

    unsigned long long w2[4][8];
    #pragma unroll
    for (int cc = 0; cc < 4; cc++) {
        const float2* wr = (const float2*)&Whh[(size_t)(cc * 512 + u) * 512];
        #pragma unroll
        for (int j = 0; j < 8; j++) {
            float2 v = wr[lane * 8 + j];
            w2[cc][j] = pk2(v.x, v.y);
        }
    }

    float cst = 0.f;

    for (int t = 0; t < 64; t++) {
        const float4* hc = (const float4*)g_h[t & 1];
        #pragma unroll
        for (int i = 0; i < 8; i++) {
            int q = i * 256 + tid;
            int bl = q >> 7;
            int k4 = q & 127;
            float4 v = __ldcg(hc + (size_t)(hf * 16 + bl) * 128 + k4);
            int k2a = 2 * k4, k2b = 2 * k4 + 1;
            sh2[((k2a & 7) * 16 + bl) * 32 + (k2a >> 3)] = make_float2(v.x, v.y);
            sh2[((k2b & 7) * 16 + bl) * 32 + (k2b >> 3)] = make_float2(v.z, v.w);
        }
        __syncthreads();

        unsigned long long a2[4][16];
        #pragma unroll
        for (int cc = 0; cc < 4; cc++)
            #pragma unroll
            for (int i = 0; i < 16; i++) a2[cc][i] = 0ull;

        #pragma unroll
        for (int j = 0; j < 8; j++) {
            #pragma unroll
            for (int bl = 0; bl < 16; bl++) {
                float2 hv = sh2[(j * 16 + bl) * 32 + lane];
                unsigned long long h2v = pk2(hv.x, hv.y);
                #pragma unroll
                for (int cc = 0; cc < 4; cc++)
                    a2[cc][bl] = ffma2(w2[cc][j], h2v, a2[cc][bl]);
            }
        }

        float gate[4];
        #pragma unroll
        for (int cc = 0; cc < 4; cc++) {
            float s[16];
            #pragma unroll
            for (int i = 0; i < 16; i++) {
                float x, y; upk2(a2[cc][i], x, y); s[i] = x + y;
            }
            int nb = 16;
            #pragma unroll
            for (int off = 8; off >= 1; off >>= 1) {
                int hn = nb >> 1;
                bool hi = (lane & off) != 0;
                #pragma unroll
                for (int i = 0; i < hn; i++) {
                    float give = hi ? s[i] : s[i + hn];
                    float keep = hi ? s[i + hn] : s[i];
                    float got  = __shfl_xor_sync(0xffffffffu, give, off);
                    s[i] = keep + got;
                }
                nb = hn;
            }
            s[0] += __shfl_xor_sync(0xffffffffu, s[0], 16);
            gate[cc] = s[0];
        }

        int row = t * 32 + b;
        #pragma unroll
        for (int cc = 0; cc < 4; cc++)
            gate[cc] += __ldg(&g_GxT[(size_t)(cc * 512 + u) * Mm + row]);

        float ig = 1.f / (1.f + expf(-gate[0]));
        float fg = 1.f / (1.f + expf(-gate[1]));
        float gg = tanhf(gate[2]);
        float og = 1.f / (1.f + expf(-gate[3]));
        cst = fg * cst + ig * gg;
        float hN = og * tanhf(cst);

        if (lane < 16) {
            g_h[(t + 1) & 1][b * 512 + u] = hN;
            int rr = b * 64 + t;
            g_hsH[(size_t)rr * 512 + u] = __float2half_rn(hN);
        }

        __threadfence();
        __syncthreads();
        if (tid == 0) {
            atomicAdd(&g_bcount, 1u);
            unsigned tgt = (unsigned)REC_CTAS * (unsigned)(t + 1);
            while (*(volatile unsigned*)&g_bcount < tgt) { __nanosleep(32); }
            __threadfence();
        }
        __syncthreads();
    }
}

// ---------------- V-GEMM: single-pass fp16 wmma, padded smem ----------------
// out[rr][v] = sum_k hs[rr][k]*Wout[v][k] + b_out[v]. One mma term (plain
// fp16 operands, fp32 accumulate). Operand tiles 128x32 halves padded to
// stride 40 (conflict-free ldmatrix). smem: 2 stages x 2 matrices x 128x40
// halves = 40 KB; epilogue reuses as 128x132 f32 padded tile (67.6 KB).
#define VST   40
#define VSMEM (128 * 132 * 4)               // 67584 B (covers both uses)
#define EPI_LD 132

__device__ __forceinline__ int vslab(int st, int mtx) {
    return (st * 2 + mtx) * (128 * VST);    // in __half units
}

__global__ __launch_bounds__(256)
void gemm_v(const float* __restrict__ b_out, float* __restrict__ out) {
    extern __shared__ __half vsm[];

    int tid = threadIdx.x, wid = tid >> 5;
    int n0 = blockIdx.x * 128, m0 = blockIdx.y * 128;
    int wm = (wid >> 2) * 64, wn = (wid & 3) * 32;

    wmma::fragment<wmma::accumulator, 16, 16, 16, float> acc[4][2];
    #pragma unroll
    for (int mi = 0; mi < 4; mi++)
        #pragma unroll
        for (int ni = 0; ni < 2; ni++)
            wmma::fill_fragment(acc[mi][ni], 0.f);

    // 2 matrices x 128 rows x 4 16B-chunks = 1024 cp.asyncs per stage
    auto loadStage = [&](int kc, int st) {
        #pragma unroll
        for (int i = 0; i < 4; i++) {
            int c   = i * 256 + tid;        // 0..1023
            int mtx = c >> 9;
            int cc  = c & 511;
            int row = cc >> 2, q = cc & 3;
            const __half* g = mtx ? g_WoutH : g_hsH;
            int rbase = mtx ? n0 : m0;
            cpa16(&vsm[vslab(st, mtx) + row * VST + q * 8],
                  g + (size_t)(rbase + row) * 512 + kc * 32 + q * 8);
        }
        asm volatile("cp.async.commit_group;\n");
    };

    loadStage(0, 0);

    #pragma unroll 1
    for (int kc = 0; kc < 16; kc++) {
        int st = kc & 1;
        asm volatile("cp.async.wait_group 0;\n");
        __syncthreads();                         // stage st ready; st^1 free
        if (kc < 15) loadStage(kc + 1, st ^ 1);  // overlaps compute below

        #pragma unroll
        for (int ks2 = 0; ks2 < 2; ks2++) {
            int ko = ks2 * 16;
            wmma::fragment<wmma::matrix_b, 16, 16, 16, __half, wmma::col_major> fb[2];
            #pragma unroll
            for (int ni = 0; ni < 2; ni++)
                wmma::load_matrix_sync(fb[ni],
                    &vsm[vslab(st, 1) + (wn + ni * 16) * VST + ko], VST);
            #pragma unroll
            for (int mi = 0; mi < 4; mi++) {
                wmma::fragment<wmma::matrix_a, 16, 16, 16, __half, wmma::row_major> fa;
                wmma::load_matrix_sync(fa,
                    &vsm[vslab(st, 0) + (wm + mi * 16) * VST + ko], VST);
                #pragma unroll
                for (int ni = 0; ni < 2; ni++)
                    wmma::mma_sync(acc[mi][ni], fa, fb[ni], acc[mi][ni]);
            }
        }
    }

    // coalesced epilogue: stage padded 128x132 f32 tile, then float4 stores
    __syncthreads();
    float* ct = (float*)vsm;
    #pragma unroll
    for (int mi = 0; mi < 4; mi++)
        #pragma unroll
        for (int ni = 0; ni < 2; ni++)
            wmma::store_matrix_sync(ct + (wm + mi * 16) * EPI_LD + (wn + ni * 16),
                                    acc[mi][ni], EPI_LD, wmma::mem_row_major);
    __syncthreads();

    #pragma unroll
    for (int it = 0; it < 16; it++) {
        int f   = it * 256 + tid;        // 0..4095 float4s
        int row = f >> 5, c4 = f & 31;
        const float* sp = ct + row * EPI_LD + c4 * 4;
        float4 v = make_float4(sp[0], sp[1], sp[2], sp[3]);
        const float4 bv = *((const float4*)(b_out + n0) + c4);
        v.x += bv.x; v.y += bv.y; v.z += bv.z; v.w += bv.w;
        *((float4*)(out + (size_t)(m0 + row) * Vv + n0) + c4) = v;
    }
}

// ---------------- launch -----------------------------------------------------
extern "C" void kernel_launch(void* const* d_in, const int* in_sizes, int n_in,
                              void* d_out, int out_size) {
    const float* feat  = (const float*)d_in[0];
    const int*   cap32 = (const int*)d_in[1];
    const float* W_ih  = (const float*)d_in[2];
    const float* W_hh  = (const float*)d_in[3];
    const float* b_ih  = (const float*)d_in[4];
    const float* b_hh  = (const float*)d_in[5];
    const float* W_out = (const float*)d_in[6];
    const float* b_out = (const float*)d_in[7];
    const float* emb   = (const float*)d_in[8];
    float* out = (float*)d_out;

    cudaFuncSetAttribute(gemm_v, cudaFuncAttributeMaxDynamicSharedMemorySize,
                         VSMEM);

    prep_misc<<<64, 256>>>(cap32, b_ih, b_hh);
    conv_weights<<<2048, 256>>>(W_ih, W_out);
    build_x<<<512, 256>>>(feat, emb);
    gemm_gx<<<dim3(G4 / 128, Mm / 128), 256>>>();
    lstm_kernel<<<REC_CTAS, 256>>>(W_hh);
    gemm_v<<<dim3(Vv / 128, Mm / 128), 256, VSMEM>>>(b_out, out);
}